// round 1
// baseline (speedup 1.0000x reference)
#include <cuda_runtime.h>

// Problem geometry (fixed per reference setup_inputs)
#define B_ 2
#define D_ 160
#define H_ 192
#define W_ 160
constexpr size_t N_   = (size_t)B_ * D_ * H_ * W_;   // 9,830,400
constexpr size_t HW_  = (size_t)H_ * W_;

// Scratch: 5 channels (I, J, I2, J2, IJ), ping-pong between passes.
__device__ float  g_A[5 * N_];
__device__ float  g_B[5 * N_];
__device__ double g_acc;

__global__ void k_init() { g_acc = 0.0; }

// ---------------------------------------------------------------------------
// Pass 1: 9-tap box sum along W (contiguous). One (b,d,h) row per warp-row.
// Reads I,J once, produces the 5 windowed fields.
// ---------------------------------------------------------------------------
__global__ void k_pass1(const float* __restrict__ I, const float* __restrict__ J) {
    __shared__ float sI[2][W_];
    __shared__ float sJ[2][W_];
    const int ty = threadIdx.y;
    const int w  = threadIdx.x;
    const size_t row  = (size_t)blockIdx.x * 2 + ty;     // b*D*H + d*H + h
    const size_t base = row * W_;

    sI[ty][w] = I[base + w];
    sJ[ty][w] = J[base + w];
    __syncthreads();

    float s0 = 0.f, s1 = 0.f, s2 = 0.f, s3 = 0.f, s4 = 0.f;
#pragma unroll
    for (int k = -4; k <= 4; k++) {
        int ww = w + k;
        if (ww >= 0 && ww < W_) {
            float a = sI[ty][ww];
            float b = sJ[ty][ww];
            s0 += a; s1 += b; s2 += a * a; s3 += b * b; s4 += a * b;
        }
    }
    const size_t o = base + w;
    g_A[0 * N_ + o] = s0;
    g_A[1 * N_ + o] = s1;
    g_A[2 * N_ + o] = s2;
    g_A[3 * N_ + o] = s3;
    g_A[4 * N_ + o] = s4;
}

// ---------------------------------------------------------------------------
// Pass 2: 9-tap box sum along H via running window.
// Thread handles a 24-high chunk of one (b,d,w) column; 8 chunks cover H=192.
// Consecutive threads -> consecutive w -> coalesced.
// ---------------------------------------------------------------------------
__global__ void k_pass2() {
    const int t    = blockIdx.x * blockDim.x + threadIdx.x;
    const int w    = t % W_;
    const int rest = t / W_;
    const int ch   = rest & 7;     // chunk 0..7
    const int col  = rest >> 3;    // b*D + d, 0..319
    const int h0   = ch * 24;
    const size_t colbase = (size_t)col * HW_ + w;

    float S[5];
#pragma unroll
    for (int c = 0; c < 5; c++) {
        float s = 0.f;
#pragma unroll
        for (int k = -4; k <= 4; k++) {
            int h = h0 + k;
            if (h >= 0 && h < H_) s += g_A[c * N_ + colbase + (size_t)h * W_];
        }
        S[c] = s;
    }

    for (int i = 0; i < 24; i++) {
        const int h = h0 + i;
        const size_t o = colbase + (size_t)h * W_;
#pragma unroll
        for (int c = 0; c < 5; c++) g_B[c * N_ + o] = S[c];
        const int hp = h + 5, hm = h - 4;
#pragma unroll
        for (int c = 0; c < 5; c++) {
            float add = (hp < H_)  ? g_A[c * N_ + colbase + (size_t)hp * W_] : 0.f;
            float sub = (hm >= 0)  ? g_A[c * N_ + colbase + (size_t)hm * W_] : 0.f;
            S[c] += add - sub;
        }
    }
}

// ---------------------------------------------------------------------------
// Pass 3: 9-tap box sum along D via running window, fused cc + reduction.
// Thread handles a 20-deep chunk of one (b,h,w) pillar; 8 chunks cover D=160.
// ---------------------------------------------------------------------------
__global__ void k_pass3() {
    const int t     = blockIdx.x * blockDim.x + threadIdx.x;
    const int w     = t % W_;
    const int rest  = t / W_;
    const int h     = rest % H_;
    const int rest2 = rest / H_;
    const int ch    = rest2 & 7;   // chunk 0..7
    const int b     = rest2 >> 3;  // batch
    const int d0    = ch * 20;
    const size_t colbase = (size_t)b * D_ * HW_ + (size_t)h * W_ + w;

    float S[5];
#pragma unroll
    for (int c = 0; c < 5; c++) {
        float s = 0.f;
#pragma unroll
        for (int k = -4; k <= 4; k++) {
            int d = d0 + k;
            if (d >= 0 && d < D_) s += g_B[c * N_ + colbase + (size_t)d * HW_];
        }
        S[c] = s;
    }

    const float inv = 1.0f / 729.0f;
    float lacc = 0.f;
    for (int i = 0; i < 20; i++) {
        const int d = d0 + i;
        // cross = IJ - I_sum*J_sum/729 ; var = x2 - x_sum^2/729  (algebraic
        // simplification of the reference's expanded form)
        float cross = S[4] - S[0] * S[1] * inv;
        float ivar  = S[2] - S[0] * S[0] * inv;
        float jvar  = S[3] - S[1] * S[1] * inv;
        lacc += cross * cross / (ivar * jvar + 1e-5f);

        const int dp = d + 5, dm = d - 4;
#pragma unroll
        for (int c = 0; c < 5; c++) {
            float add = (dp < D_)  ? g_B[c * N_ + colbase + (size_t)dp * HW_] : 0.f;
            float sub = (dm >= 0)  ? g_B[c * N_ + colbase + (size_t)dm * HW_] : 0.f;
            S[c] += add - sub;
        }
    }

    // Block reduction in double, one atomic per block.
    double v = (double)lacc;
#pragma unroll
    for (int off = 16; off; off >>= 1)
        v += __shfl_down_sync(0xffffffffu, v, off);

    __shared__ double sm[8];
    const int lane = threadIdx.x & 31;
    const int wid  = threadIdx.x >> 5;
    if (lane == 0) sm[wid] = v;
    __syncthreads();
    if (wid == 0) {
        v = (lane < (int)(blockDim.x >> 5)) ? sm[lane] : 0.0;
#pragma unroll
        for (int off = 4; off; off >>= 1)
            v += __shfl_down_sync(0xffffffffu, v, off);
        if (lane == 0) atomicAdd(&g_acc, v);
    }
}

__global__ void k_final(float* out) {
    out[0] = (float)(-g_acc / (double)N_);
}

// ---------------------------------------------------------------------------
extern "C" void kernel_launch(void* const* d_in, const int* in_sizes, int n_in,
                              void* d_out, int out_size) {
    const float* y_pred = (const float*)d_in[0];
    const float* y_true = (const float*)d_in[1];

    k_init<<<1, 1>>>();

    dim3 b1(W_, 2);
    k_pass1<<<(B_ * D_ * H_) / 2, b1>>>(y_true, y_pred);   // I = y_true, J = y_pred

    // pass2: B*D*8*W threads = 409600
    k_pass2<<<(B_ * D_ * 8 * W_) / 256, 256>>>();

    // pass3: B*8*H*W threads = 491520
    k_pass3<<<(B_ * 8 * H_ * W_) / 256, 256>>>();

    k_final<<<1, 1>>>((float*)d_out);
}

// round 2
// speedup vs baseline: 1.0805x; 1.0805x over previous
#include <cuda_runtime.h>

// Problem geometry (fixed per reference setup_inputs)
#define B_ 2
#define D_ 160
#define H_ 192
#define W_ 160
constexpr size_t N_  = (size_t)B_ * D_ * H_ * W_;   // 9,830,400
constexpr size_t HW_ = (size_t)H_ * W_;

// Intermediate: 5 channels (I_s, J_s, I2_s, J2_s, IJ_s), W+H convolved.
__device__ float  g_A[5 * N_];
__device__ double g_acc;

__global__ void k_init() { g_acc = 0.0; }

// ---------------------------------------------------------------------------
// Fused pass 1+2: 9-tap box sum along W and H.
// One block per (b,d) plane; one thread per w column. Thread slides along h
// with a register ring buffer (statically indexed via unroll-by-9), so each
// input element is read from DRAM once and each intermediate written once.
// ---------------------------------------------------------------------------
__global__ void __launch_bounds__(W_) k_p12(const float* __restrict__ I,
                                            const float* __restrict__ J) {
    const int w = threadIdx.x;              // 0..159
    const size_t pbase = (size_t)blockIdx.x * HW_;   // (b*D + d) plane
    const float* __restrict__ Ip = I + pbase;
    const float* __restrict__ Jp = J + pbase;

    float r0[9], r1[9], r2[9], r3[9], r4[9];
#pragma unroll
    for (int j = 0; j < 9; j++) { r0[j]=0.f; r1[j]=0.f; r2[j]=0.f; r3[j]=0.f; r4[j]=0.f; }
    float S0=0.f, S1=0.f, S2=0.f, S3=0.f, S4=0.f;

    // hr sweeps 0..197; output at h_out = hr-4 (valid 0..191, needs hr<=195)
#pragma unroll 1
    for (int hb = 0; hb < 198; hb += 9) {
#pragma unroll
        for (int j = 0; j < 9; j++) {
            const int hr = hb + j;
            float w0=0.f, w1=0.f, w2=0.f, w3=0.f, w4=0.f;
            if (hr < H_) {
                const float* ri = Ip + (size_t)hr * W_;
                const float* rj = Jp + (size_t)hr * W_;
#pragma unroll
                for (int k = -4; k <= 4; k++) {
                    const int ww = w + k;
                    if (ww >= 0 && ww < W_) {
                        const float a = __ldg(ri + ww);
                        const float b = __ldg(rj + ww);
                        w0 += a; w1 += b;
                        w2 = fmaf(a, a, w2);
                        w3 = fmaf(b, b, w3);
                        w4 = fmaf(a, b, w4);
                    }
                }
            }
            S0 += w0 - r0[j]; r0[j] = w0;
            S1 += w1 - r1[j]; r1[j] = w1;
            S2 += w2 - r2[j]; r2[j] = w2;
            S3 += w3 - r3[j]; r3[j] = w3;
            S4 += w4 - r4[j]; r4[j] = w4;

            const int ho = hr - 4;
            if (ho >= 0 && ho < H_) {
                const size_t o = pbase + (size_t)ho * W_ + w;
                g_A[0*N_ + o] = S0;
                g_A[1*N_ + o] = S1;
                g_A[2*N_ + o] = S2;
                g_A[3*N_ + o] = S3;
                g_A[4*N_ + o] = S4;
            }
        }
    }
}

// ---------------------------------------------------------------------------
// Pass 3: 9-tap box sum along D via register-ring sliding window, fused cc
// computation + block reduction. Each intermediate element read exactly once.
// Thread owns one (b,h,w) pillar; warp = 32 consecutive w -> coalesced.
// ---------------------------------------------------------------------------
__global__ void __launch_bounds__(256) k_p3() {
    const int t = blockIdx.x * blockDim.x + threadIdx.x;   // 61440 threads
    const int w = t % W_;
    const int h = (t / W_) % H_;
    const int b = t / (W_ * H_);
    const size_t colbase = (size_t)b * D_ * HW_ + (size_t)h * W_ + w;

    float r0[9], r1[9], r2[9], r3[9], r4[9];
#pragma unroll
    for (int j = 0; j < 9; j++) { r0[j]=0.f; r1[j]=0.f; r2[j]=0.f; r3[j]=0.f; r4[j]=0.f; }
    float S0=0.f, S1=0.f, S2=0.f, S3=0.f, S4=0.f;

    const float inv = 1.0f / 729.0f;
    float lacc = 0.f;

    // dr sweeps 0..170; output at d_out = dr-4 (valid 0..159, needs dr<=163)
#pragma unroll 1
    for (int db = 0; db < 171; db += 9) {
#pragma unroll
        for (int j = 0; j < 9; j++) {
            const int dr = db + j;
            float v0=0.f, v1=0.f, v2=0.f, v3=0.f, v4=0.f;
            if (dr < D_) {
                const size_t o = colbase + (size_t)dr * HW_;
                v0 = g_A[0*N_ + o];
                v1 = g_A[1*N_ + o];
                v2 = g_A[2*N_ + o];
                v3 = g_A[3*N_ + o];
                v4 = g_A[4*N_ + o];
            }
            S0 += v0 - r0[j]; r0[j] = v0;
            S1 += v1 - r1[j]; r1[j] = v1;
            S2 += v2 - r2[j]; r2[j] = v2;
            S3 += v3 - r3[j]; r3[j] = v3;
            S4 += v4 - r4[j]; r4[j] = v4;

            const int dd = dr - 4;
            if (dd >= 0 && dd < D_) {
                // cross = IJ - I_sum*J_sum/729 ; var = x2 - x_sum^2/729
                const float cross = fmaf(-S0 * inv, S1, S4);
                const float ivar  = fmaf(-S0 * inv, S0, S2);
                const float jvar  = fmaf(-S1 * inv, S1, S3);
                lacc += __fdividef(cross * cross, fmaf(ivar, jvar, 1e-5f));
            }
        }
    }

    // Block reduction in double, one atomic per block.
    double v = (double)lacc;
#pragma unroll
    for (int off = 16; off; off >>= 1)
        v += __shfl_down_sync(0xffffffffu, v, off);

    __shared__ double sm[8];
    const int lane = threadIdx.x & 31;
    const int wid  = threadIdx.x >> 5;
    if (lane == 0) sm[wid] = v;
    __syncthreads();
    if (wid == 0) {
        v = (lane < (int)(blockDim.x >> 5)) ? sm[lane] : 0.0;
#pragma unroll
        for (int off = 4; off; off >>= 1)
            v += __shfl_down_sync(0xffffffffu, v, off);
        if (lane == 0) atomicAdd(&g_acc, v);
    }
}

__global__ void k_final(float* out) {
    out[0] = (float)(-g_acc / (double)N_);
}

// ---------------------------------------------------------------------------
extern "C" void kernel_launch(void* const* d_in, const int* in_sizes, int n_in,
                              void* d_out, int out_size) {
    const float* y_pred = (const float*)d_in[0];
    const float* y_true = (const float*)d_in[1];

    k_init<<<1, 1>>>();

    // I = y_true, J = y_pred (cc formula is symmetric anyway)
    k_p12<<<B_ * D_, W_>>>(y_true, y_pred);

    k_p3<<<(B_ * H_ * W_) / 256, 256>>>();

    k_final<<<1, 1>>>((float*)d_out);
}

// round 3
// speedup vs baseline: 1.7322x; 1.6031x over previous
#include <cuda_runtime.h>

// Problem geometry (fixed per reference setup_inputs)
#define B_ 2
#define D_ 160
#define H_ 192
#define W_ 160
constexpr size_t N_  = (size_t)B_ * D_ * H_ * W_;   // 9,830,400
constexpr size_t HW_ = (size_t)H_ * W_;

// Intermediate: 5 channels (I_s, J_s, I2_s, J2_s, IJ_s), W+H convolved.
__device__ float  g_A[5 * N_];
__device__ double g_acc;

__global__ void k_init() { g_acc = 0.0; }

// ---------------------------------------------------------------------------
// Fused pass 1+2: 9-tap box sum along W and H.
// Task = (plane, h-chunk of 24 output rows). 2560 tasks x 160 threads = 410K
// threads. Thread = one w column; slides along h with a register ring
// (statically indexed via unroll-by-9; 36 pushes, 32 useful, outputs at
// push index 8..31). Halo rows between chunks are absorbed by L2.
// ---------------------------------------------------------------------------
__global__ void __launch_bounds__(W_) k_p12(const float* __restrict__ I,
                                            const float* __restrict__ J) {
    const int task  = blockIdx.x;          // 0..2559
    const int plane = task >> 3;           // b*D + d
    const int h0    = (task & 7) * 24;     // first output row of this chunk
    const int w     = threadIdx.x;         // 0..159

    const size_t pbase = (size_t)plane * HW_;
    const float* __restrict__ Ip = I + pbase;
    const float* __restrict__ Jp = J + pbase;

    float r0[9], r1[9], r2[9], r3[9], r4[9];
#pragma unroll
    for (int j = 0; j < 9; j++) { r0[j]=0.f; r1[j]=0.f; r2[j]=0.f; r3[j]=0.f; r4[j]=0.f; }
    float S0=0.f, S1=0.f, S2=0.f, S3=0.f, S4=0.f;

#pragma unroll 1
    for (int ib = 0; ib < 36; ib += 9) {
#pragma unroll
        for (int j = 0; j < 9; j++) {
            const int idx = ib + j;             // push index 0..35
            const int hr  = h0 - 4 + idx;       // input row being W-windowed
            float w0=0.f, w1=0.f, w2=0.f, w3=0.f, w4=0.f;
            if (idx < 32 && hr >= 0 && hr < H_) {
                const float* ri = Ip + (size_t)hr * W_;
                const float* rj = Jp + (size_t)hr * W_;
#pragma unroll
                for (int k = -4; k <= 4; k++) {
                    const int ww = w + k;
                    if (ww >= 0 && ww < W_) {
                        const float a = __ldg(ri + ww);
                        const float b = __ldg(rj + ww);
                        w0 += a; w1 += b;
                        w2 = fmaf(a, a, w2);
                        w3 = fmaf(b, b, w3);
                        w4 = fmaf(a, b, w4);
                    }
                }
            }
            S0 += w0 - r0[j]; r0[j] = w0;
            S1 += w1 - r1[j]; r1[j] = w1;
            S2 += w2 - r2[j]; r2[j] = w2;
            S3 += w3 - r3[j]; r3[j] = w3;
            S4 += w4 - r4[j]; r4[j] = w4;

            // output row ho = hr - 4; valid for push idx in [8, 32)
            if (idx >= 8 && idx < 32) {
                const int ho = hr - 4;
                const size_t o = pbase + (size_t)ho * W_ + w;
                g_A[0*N_ + o] = S0;
                g_A[1*N_ + o] = S1;
                g_A[2*N_ + o] = S2;
                g_A[3*N_ + o] = S3;
                g_A[4*N_ + o] = S4;
            }
        }
    }
}

// ---------------------------------------------------------------------------
// Pass 3: 9-tap box sum along D, float4-vectorized over w, d-chunked x8,
// re-read sliding window (S += x[d+5] - x[d-4]; both loads are pure functions
// of d -> fully independent -> deep MLP). Subtract-stream re-reads hit L2
// (9-slice working set ~5.5MB). Fused cc + block reduction.
// ---------------------------------------------------------------------------
__global__ void __launch_bounds__(128) k_p3() {
    const int t  = blockIdx.x * blockDim.x + threadIdx.x;  // 122,880 threads
    const int wv = t % 40;                    // float4 group along w
    const int h  = (t / 40) % H_;
    const int ch = (t / (40 * H_)) & 7;       // d-chunk 0..7 (20 outputs each)
    const int b  = t / (40 * H_ * 8);
    const int d0 = ch * 20;

    const size_t colbase = (size_t)b * D_ * HW_ + (size_t)h * W_ + (size_t)wv * 4;

    float4 S[5];
#pragma unroll
    for (int c = 0; c < 5; c++) S[c] = make_float4(0.f, 0.f, 0.f, 0.f);

    // Prologue: direct 9-tap sum for output d0 (rows d0-4 .. d0+4)
#pragma unroll
    for (int k = -4; k <= 4; k++) {
        const int d = d0 + k;
        if (d >= 0 && d < D_) {
            const size_t o = colbase + (size_t)d * HW_;
#pragma unroll
            for (int c = 0; c < 5; c++) {
                const float4 v = *(const float4*)&g_A[c * N_ + o];
                S[c].x += v.x; S[c].y += v.y; S[c].z += v.z; S[c].w += v.w;
            }
        }
    }

    const float inv = 1.0f / 729.0f;
    float lacc = 0.f;

#pragma unroll 4
    for (int i = 0; i < 20; i++) {
        const int d  = d0 + i;
        const int dp = d + 5;
        const int dm = d - 4;

        // Issue next window's loads first (independent of S) for MLP.
        float4 av[5], sv[5];
        const bool pok = (dp < D_);
        const bool mok = (dm >= 0);
        const size_t op = colbase + (size_t)(pok ? dp : 0) * HW_;
        const size_t om = colbase + (size_t)(mok ? dm : 0) * HW_;
#pragma unroll
        for (int c = 0; c < 5; c++) {
            av[c] = pok ? *(const float4*)&g_A[c * N_ + op] : make_float4(0.f,0.f,0.f,0.f);
            sv[c] = mok ? *(const float4*)&g_A[c * N_ + om] : make_float4(0.f,0.f,0.f,0.f);
        }

        // cc for current output d (4 lanes)
        {
            const float* s0 = (const float*)&S[0];
            const float* s1 = (const float*)&S[1];
            const float* s2 = (const float*)&S[2];
            const float* s3 = (const float*)&S[3];
            const float* s4 = (const float*)&S[4];
#pragma unroll
            for (int l = 0; l < 4; l++) {
                const float cross = fmaf(-s0[l] * inv, s1[l], s4[l]);
                const float ivar  = fmaf(-s0[l] * inv, s0[l], s2[l]);
                const float jvar  = fmaf(-s1[l] * inv, s1[l], s3[l]);
                lacc += __fdividef(cross * cross, fmaf(ivar, jvar, 1e-5f));
            }
        }

        // Slide window
#pragma unroll
        for (int c = 0; c < 5; c++) {
            S[c].x += av[c].x - sv[c].x;
            S[c].y += av[c].y - sv[c].y;
            S[c].z += av[c].z - sv[c].z;
            S[c].w += av[c].w - sv[c].w;
        }
    }

    // Block reduction in double, one atomic per block.
    double v = (double)lacc;
#pragma unroll
    for (int off = 16; off; off >>= 1)
        v += __shfl_down_sync(0xffffffffu, v, off);

    __shared__ double sm[4];
    const int lane = threadIdx.x & 31;
    const int wid  = threadIdx.x >> 5;
    if (lane == 0) sm[wid] = v;
    __syncthreads();
    if (wid == 0) {
        v = (lane < 4) ? sm[lane] : 0.0;
        v += __shfl_down_sync(0xffffffffu, v, 2);
        v += __shfl_down_sync(0xffffffffu, v, 1);
        if (lane == 0) atomicAdd(&g_acc, v);
    }
}

__global__ void k_final(float* out) {
    out[0] = (float)(-g_acc / (double)N_);
}

// ---------------------------------------------------------------------------
extern "C" void kernel_launch(void* const* d_in, const int* in_sizes, int n_in,
                              void* d_out, int out_size) {
    const float* y_pred = (const float*)d_in[0];
    const float* y_true = (const float*)d_in[1];

    k_init<<<1, 1>>>();

    // 2560 tasks (320 planes x 8 h-chunks), 160 threads each
    k_p12<<<2560, W_>>>(y_true, y_pred);

    // 122,880 threads: (b, d-chunk, h, w/4)
    k_p3<<<(B_ * 8 * H_ * 40) / 128, 128>>>();

    k_final<<<1, 1>>>((float*)d_out);
}

// round 4
// speedup vs baseline: 2.2787x; 1.3155x over previous
#include <cuda_runtime.h>

// Problem geometry (fixed per reference setup_inputs)
#define B_ 2
#define D_ 160
#define H_ 192
#define W_ 160
constexpr size_t N_  = (size_t)B_ * D_ * H_ * W_;   // 9,830,400
constexpr size_t HW_ = (size_t)H_ * W_;
#define WG_ 40   // float4 groups along w

// Intermediate: 5 channels (I_s, J_s, I2_s, J2_s, IJ_s), W+H convolved.
__device__ float  g_A[5 * N_];
__device__ double g_acc;

// ---------------------------------------------------------------------------
// Helpers
// ---------------------------------------------------------------------------
__device__ __forceinline__ float4 f4z() { return make_float4(0.f, 0.f, 0.f, 0.f); }

// 9-tap window sums per lane from a 12-float sequence x[0..11] (x[0] = w-4).
// lane l output = sum x[l .. l+8].
__device__ __forceinline__ float4 win9(const float* x) {
    float s = x[0]+x[1]+x[2]+x[3]+x[4]+x[5]+x[6]+x[7]+x[8];
    float4 r;
    r.x = s;
    s += x[9]  - x[0]; r.y = s;
    s += x[10] - x[1]; r.z = s;
    s += x[11] - x[2]; r.w = s;
    return r;
}

// ---------------------------------------------------------------------------
// Fused pass 1+2: 9-tap box sums along W and H, float4-vectorized.
// Thread = (plane, h-chunk of 24, 4-wide w group). Slides along h via
// re-read: S += Wrow(h+5) - Wrow(h-4). The subtract row was loaded 9
// iterations earlier -> L1/L2 hit, DRAM read stays ~2N.
// ---------------------------------------------------------------------------
__global__ void __launch_bounds__(256) k_p12(const float* __restrict__ I,
                                             const float* __restrict__ J) {
    const int t     = blockIdx.x * blockDim.x + threadIdx.x;  // 102,400 threads
    const int g     = t % WG_;                 // f4 group 0..39
    const int ch    = (t / WG_) & 7;           // h-chunk 0..7
    const int plane = t / (WG_ * 8);           // b*D + d
    const int h0    = ch * 24;

    if (t == 0) g_acc = 0.0;   // p3 runs after p12 (stream-ordered)

    const size_t pbase = (size_t)plane * HW_;
    const float4* __restrict__ I4 = (const float4*)(I + pbase);
    const float4* __restrict__ J4 = (const float4*)(J + pbase);

    float4 S0 = f4z(), S1 = f4z(), S2 = f4z(), S3 = f4z(), S4 = f4z();

    // Per-row accumulation: loads taps w-4..w+7 (3 aligned float4 per field),
    // forms products, windows each channel, adds sign*window into S.
    auto accum = [&](int hr, float sg) {
        const int rb = hr * WG_;                 // float4 row base
        float4 qa0 = (g > 0)       ? __ldg(I4 + rb + g - 1) : f4z();
        float4 qa1 =                 __ldg(I4 + rb + g);
        float4 qa2 = (g < WG_ - 1) ? __ldg(I4 + rb + g + 1) : f4z();
        float4 qb0 = (g > 0)       ? __ldg(J4 + rb + g - 1) : f4z();
        float4 qb1 =                 __ldg(J4 + rb + g);
        float4 qb2 = (g < WG_ - 1) ? __ldg(J4 + rb + g + 1) : f4z();

        float a[12] = {qa0.x,qa0.y,qa0.z,qa0.w, qa1.x,qa1.y,qa1.z,qa1.w, qa2.x,qa2.y,qa2.z,qa2.w};
        float b[12] = {qb0.x,qb0.y,qb0.z,qb0.w, qb1.x,qb1.y,qb1.z,qb1.w, qb2.x,qb2.y,qb2.z,qb2.w};

        float4 w0 = win9(a);
        float4 w1 = win9(b);
        float p[12];
#pragma unroll
        for (int i = 0; i < 12; i++) p[i] = a[i] * a[i];
        float4 w2 = win9(p);
#pragma unroll
        for (int i = 0; i < 12; i++) p[i] = b[i] * b[i];
        float4 w3 = win9(p);
#pragma unroll
        for (int i = 0; i < 12; i++) p[i] = a[i] * b[i];
        float4 w4 = win9(p);

        S0.x += sg*w0.x; S0.y += sg*w0.y; S0.z += sg*w0.z; S0.w += sg*w0.w;
        S1.x += sg*w1.x; S1.y += sg*w1.y; S1.z += sg*w1.z; S1.w += sg*w1.w;
        S2.x += sg*w2.x; S2.y += sg*w2.y; S2.z += sg*w2.z; S2.w += sg*w2.w;
        S3.x += sg*w3.x; S3.y += sg*w3.y; S3.z += sg*w3.z; S3.w += sg*w3.w;
        S4.x += sg*w4.x; S4.y += sg*w4.y; S4.z += sg*w4.z; S4.w += sg*w4.w;
    };

    // Prologue: window for output row h0 (rows h0-4 .. h0+4)
#pragma unroll
    for (int k = -4; k <= 4; k++) {
        const int hr = h0 + k;
        if (hr >= 0 && hr < H_) accum(hr, 1.f);
    }

#pragma unroll 2
    for (int i = 0; i < 24; i++) {
        const int h = h0 + i;
        const size_t o = pbase + (size_t)h * W_ + (size_t)g * 4;
        *(float4*)&g_A[0*N_ + o] = S0;
        *(float4*)&g_A[1*N_ + o] = S1;
        *(float4*)&g_A[2*N_ + o] = S2;
        *(float4*)&g_A[3*N_ + o] = S3;
        *(float4*)&g_A[4*N_ + o] = S4;

        const int hp = h + 5, hm = h - 4;
        if (hp < H_)  accum(hp,  1.f);
        if (hm >= 0)  accum(hm, -1.f);
    }
}

// ---------------------------------------------------------------------------
// Pass 3: 9-tap box sum along D, float4 over w, d-chunked x8, re-read sliding
// window (independent loads -> deep MLP). Fused cc + block reduction.
// ---------------------------------------------------------------------------
__global__ void __launch_bounds__(128) k_p3() {
    const int t  = blockIdx.x * blockDim.x + threadIdx.x;  // 122,880 threads
    const int wv = t % WG_;
    const int h  = (t / WG_) % H_;
    const int ch = (t / (WG_ * H_)) & 7;      // d-chunk 0..7 (20 outputs each)
    const int b  = t / (WG_ * H_ * 8);
    const int d0 = ch * 20;

    const size_t colbase = (size_t)b * D_ * HW_ + (size_t)h * W_ + (size_t)wv * 4;

    float4 S[5];
#pragma unroll
    for (int c = 0; c < 5; c++) S[c] = f4z();

#pragma unroll
    for (int k = -4; k <= 4; k++) {
        const int d = d0 + k;
        if (d >= 0 && d < D_) {
            const size_t o = colbase + (size_t)d * HW_;
#pragma unroll
            for (int c = 0; c < 5; c++) {
                const float4 v = *(const float4*)&g_A[c * N_ + o];
                S[c].x += v.x; S[c].y += v.y; S[c].z += v.z; S[c].w += v.w;
            }
        }
    }

    const float inv = 1.0f / 729.0f;
    float lacc = 0.f;

#pragma unroll 4
    for (int i = 0; i < 20; i++) {
        const int d  = d0 + i;
        const int dp = d + 5;
        const int dm = d - 4;

        float4 av[5], sv[5];
        const bool pok = (dp < D_);
        const bool mok = (dm >= 0);
        const size_t op = colbase + (size_t)(pok ? dp : 0) * HW_;
        const size_t om = colbase + (size_t)(mok ? dm : 0) * HW_;
#pragma unroll
        for (int c = 0; c < 5; c++) {
            av[c] = pok ? *(const float4*)&g_A[c * N_ + op] : f4z();
            sv[c] = mok ? *(const float4*)&g_A[c * N_ + om] : f4z();
        }

        {
            const float* s0 = (const float*)&S[0];
            const float* s1 = (const float*)&S[1];
            const float* s2 = (const float*)&S[2];
            const float* s3 = (const float*)&S[3];
            const float* s4 = (const float*)&S[4];
#pragma unroll
            for (int l = 0; l < 4; l++) {
                const float cross = fmaf(-s0[l] * inv, s1[l], s4[l]);
                const float ivar  = fmaf(-s0[l] * inv, s0[l], s2[l]);
                const float jvar  = fmaf(-s1[l] * inv, s1[l], s3[l]);
                lacc += __fdividef(cross * cross, fmaf(ivar, jvar, 1e-5f));
            }
        }

#pragma unroll
        for (int c = 0; c < 5; c++) {
            S[c].x += av[c].x - sv[c].x;
            S[c].y += av[c].y - sv[c].y;
            S[c].z += av[c].z - sv[c].z;
            S[c].w += av[c].w - sv[c].w;
        }
    }

    double v = (double)lacc;
#pragma unroll
    for (int off = 16; off; off >>= 1)
        v += __shfl_down_sync(0xffffffffu, v, off);

    __shared__ double sm[4];
    const int lane = threadIdx.x & 31;
    const int wid  = threadIdx.x >> 5;
    if (lane == 0) sm[wid] = v;
    __syncthreads();
    if (wid == 0) {
        v = (lane < 4) ? sm[lane] : 0.0;
        v += __shfl_down_sync(0xffffffffu, v, 2);
        v += __shfl_down_sync(0xffffffffu, v, 1);
        if (lane == 0) atomicAdd(&g_acc, v);
    }
}

__global__ void k_final(float* out) {
    out[0] = (float)(-g_acc / (double)N_);
}

// ---------------------------------------------------------------------------
extern "C" void kernel_launch(void* const* d_in, const int* in_sizes, int n_in,
                              void* d_out, int out_size) {
    const float* y_pred = (const float*)d_in[0];
    const float* y_true = (const float*)d_in[1];

    // 102,400 threads: (plane, h-chunk, w/4)
    k_p12<<<(B_ * D_ * 8 * WG_) / 256, 256>>>(y_true, y_pred);

    // 122,880 threads: (b, d-chunk, h, w/4)
    k_p3<<<(B_ * 8 * H_ * WG_) / 128, 128>>>();

    k_final<<<1, 1>>>((float*)d_out);
}

// round 5
// speedup vs baseline: 3.2463x; 1.4246x over previous
#include <cuda_runtime.h>
#include <cuda_fp16.h>

// Problem geometry (fixed per reference setup_inputs)
#define B_ 2
#define D_ 160
#define H_ 192
#define W_ 160
constexpr size_t N_  = (size_t)B_ * D_ * H_ * W_;   // 9,830,400
constexpr size_t HW_ = (size_t)H_ * W_;
#define WG_ 40   // float4 groups along w

// Intermediate: 5 channels (I_s, J_s, I2_s, J2_s, IJ_s), W+H convolved, fp16.
__device__ __half g_A[5 * N_];
__device__ double g_acc;

// ---------------------------------------------------------------------------
// Helpers
// ---------------------------------------------------------------------------
__device__ __forceinline__ float4 f4z() { return make_float4(0.f, 0.f, 0.f, 0.f); }

__device__ __forceinline__ uint2 f4_to_h4(float4 v) {
    __half2 lo = __floats2half2_rn(v.x, v.y);
    __half2 hi = __floats2half2_rn(v.z, v.w);
    uint2 r;
    r.x = *(const unsigned*)&lo;
    r.y = *(const unsigned*)&hi;
    return r;
}

__device__ __forceinline__ float4 h4_to_f4(uint2 u) {
    __half2 lo = *(const __half2*)&u.x;
    __half2 hi = *(const __half2*)&u.y;
    float2 a = __half22float2(lo);
    float2 b = __half22float2(hi);
    return make_float4(a.x, a.y, b.x, b.y);
}

// 9-tap window sums per lane from a 12-float sequence x[0..11] (x[0] = w-4).
__device__ __forceinline__ float4 win9(const float* x) {
    float s = x[0]+x[1]+x[2]+x[3]+x[4]+x[5]+x[6]+x[7]+x[8];
    float4 r;
    r.x = s;
    s += x[9]  - x[0]; r.y = s;
    s += x[10] - x[1]; r.z = s;
    s += x[11] - x[2]; r.w = s;
    return r;
}

// ---------------------------------------------------------------------------
// Fused pass 1+2: 9-tap box sums along W and H, float4-vectorized, fp16 out.
// Thread = (plane, h-chunk of 24, 4-wide w group). Slides along h via
// re-read: S += Wrow(h+5) - Wrow(h-4) (subtract row is an L1/L2 hit).
// ---------------------------------------------------------------------------
__global__ void __launch_bounds__(256) k_p12(const float* __restrict__ I,
                                             const float* __restrict__ J) {
    const int t     = blockIdx.x * blockDim.x + threadIdx.x;  // 102,400 threads
    const int g     = t % WG_;                 // f4 group 0..39
    const int ch    = (t / WG_) & 7;           // h-chunk 0..7
    const int plane = t / (WG_ * 8);           // b*D + d
    const int h0    = ch * 24;

    if (t == 0) g_acc = 0.0;   // p3 runs after p12 (stream-ordered)

    const size_t pbase = (size_t)plane * HW_;
    const float4* __restrict__ I4 = (const float4*)(I + pbase);
    const float4* __restrict__ J4 = (const float4*)(J + pbase);

    float4 S0 = f4z(), S1 = f4z(), S2 = f4z(), S3 = f4z(), S4 = f4z();

    auto accum = [&](int hr, float sg) {
        const int rb = hr * WG_;
        float4 qa0 = (g > 0)       ? __ldg(I4 + rb + g - 1) : f4z();
        float4 qa1 =                 __ldg(I4 + rb + g);
        float4 qa2 = (g < WG_ - 1) ? __ldg(I4 + rb + g + 1) : f4z();
        float4 qb0 = (g > 0)       ? __ldg(J4 + rb + g - 1) : f4z();
        float4 qb1 =                 __ldg(J4 + rb + g);
        float4 qb2 = (g < WG_ - 1) ? __ldg(J4 + rb + g + 1) : f4z();

        float a[12] = {qa0.x,qa0.y,qa0.z,qa0.w, qa1.x,qa1.y,qa1.z,qa1.w, qa2.x,qa2.y,qa2.z,qa2.w};
        float b[12] = {qb0.x,qb0.y,qb0.z,qb0.w, qb1.x,qb1.y,qb1.z,qb1.w, qb2.x,qb2.y,qb2.z,qb2.w};

        float4 w0 = win9(a);
        float4 w1 = win9(b);
        float p[12];
#pragma unroll
        for (int i = 0; i < 12; i++) p[i] = a[i] * a[i];
        float4 w2 = win9(p);
#pragma unroll
        for (int i = 0; i < 12; i++) p[i] = b[i] * b[i];
        float4 w3 = win9(p);
#pragma unroll
        for (int i = 0; i < 12; i++) p[i] = a[i] * b[i];
        float4 w4 = win9(p);

        S0.x += sg*w0.x; S0.y += sg*w0.y; S0.z += sg*w0.z; S0.w += sg*w0.w;
        S1.x += sg*w1.x; S1.y += sg*w1.y; S1.z += sg*w1.z; S1.w += sg*w1.w;
        S2.x += sg*w2.x; S2.y += sg*w2.y; S2.z += sg*w2.z; S2.w += sg*w2.w;
        S3.x += sg*w3.x; S3.y += sg*w3.y; S3.z += sg*w3.z; S3.w += sg*w3.w;
        S4.x += sg*w4.x; S4.y += sg*w4.y; S4.z += sg*w4.z; S4.w += sg*w4.w;
    };

    // Prologue: window for output row h0 (rows h0-4 .. h0+4)
#pragma unroll
    for (int k = -4; k <= 4; k++) {
        const int hr = h0 + k;
        if (hr >= 0 && hr < H_) accum(hr, 1.f);
    }

#pragma unroll 2
    for (int i = 0; i < 24; i++) {
        const int h = h0 + i;
        const size_t o = pbase + (size_t)h * W_ + (size_t)g * 4;
        *(uint2*)&g_A[0*N_ + o] = f4_to_h4(S0);
        *(uint2*)&g_A[1*N_ + o] = f4_to_h4(S1);
        *(uint2*)&g_A[2*N_ + o] = f4_to_h4(S2);
        *(uint2*)&g_A[3*N_ + o] = f4_to_h4(S3);
        *(uint2*)&g_A[4*N_ + o] = f4_to_h4(S4);

        const int hp = h + 5, hm = h - 4;
        if (hp < H_)  accum(hp,  1.f);
        if (hm >= 0)  accum(hm, -1.f);
    }
}

// ---------------------------------------------------------------------------
// Pass 3: 9-tap box sum along D over fp16 intermediates (fp32 accumulation),
// float4 over w, d-chunked x8, re-read sliding window. Fused cc + reduction.
// ---------------------------------------------------------------------------
__global__ void __launch_bounds__(256) k_p3() {
    const int t  = blockIdx.x * blockDim.x + threadIdx.x;  // 122,880 threads
    const int wv = t % WG_;
    const int h  = (t / WG_) % H_;
    const int ch = (t / (WG_ * H_)) & 7;      // d-chunk 0..7 (20 outputs each)
    const int b  = t / (WG_ * H_ * 8);
    const int d0 = ch * 20;

    const size_t colbase = (size_t)b * D_ * HW_ + (size_t)h * W_ + (size_t)wv * 4;

    float4 S[5];
#pragma unroll
    for (int c = 0; c < 5; c++) S[c] = f4z();

#pragma unroll
    for (int k = -4; k <= 4; k++) {
        const int d = d0 + k;
        if (d >= 0 && d < D_) {
            const size_t o = colbase + (size_t)d * HW_;
#pragma unroll
            for (int c = 0; c < 5; c++) {
                const float4 v = h4_to_f4(__ldg((const uint2*)&g_A[c * N_ + o]));
                S[c].x += v.x; S[c].y += v.y; S[c].z += v.z; S[c].w += v.w;
            }
        }
    }

    const float inv = 1.0f / 729.0f;
    float lacc = 0.f;

#pragma unroll 4
    for (int i = 0; i < 20; i++) {
        const int d  = d0 + i;
        const int dp = d + 5;
        const int dm = d - 4;

        float4 av[5], sv[5];
        const bool pok = (dp < D_);
        const bool mok = (dm >= 0);
        const size_t op = colbase + (size_t)(pok ? dp : 0) * HW_;
        const size_t om = colbase + (size_t)(mok ? dm : 0) * HW_;
#pragma unroll
        for (int c = 0; c < 5; c++) {
            av[c] = pok ? h4_to_f4(__ldg((const uint2*)&g_A[c * N_ + op])) : f4z();
            sv[c] = mok ? h4_to_f4(__ldg((const uint2*)&g_A[c * N_ + om])) : f4z();
        }

        {
            const float* s0 = (const float*)&S[0];
            const float* s1 = (const float*)&S[1];
            const float* s2 = (const float*)&S[2];
            const float* s3 = (const float*)&S[3];
            const float* s4 = (const float*)&S[4];
#pragma unroll
            for (int l = 0; l < 4; l++) {
                const float cross = fmaf(-s0[l] * inv, s1[l], s4[l]);
                const float ivar  = fmaf(-s0[l] * inv, s0[l], s2[l]);
                const float jvar  = fmaf(-s1[l] * inv, s1[l], s3[l]);
                lacc += __fdividef(cross * cross, fmaf(ivar, jvar, 1e-5f));
            }
        }

#pragma unroll
        for (int c = 0; c < 5; c++) {
            S[c].x += av[c].x - sv[c].x;
            S[c].y += av[c].y - sv[c].y;
            S[c].z += av[c].z - sv[c].z;
            S[c].w += av[c].w - sv[c].w;
        }
    }

    double v = (double)lacc;
#pragma unroll
    for (int off = 16; off; off >>= 1)
        v += __shfl_down_sync(0xffffffffu, v, off);

    __shared__ double sm[8];
    const int lane = threadIdx.x & 31;
    const int wid  = threadIdx.x >> 5;
    if (lane == 0) sm[wid] = v;
    __syncthreads();
    if (wid == 0) {
        v = (lane < 8) ? sm[lane] : 0.0;
        v += __shfl_down_sync(0xffffffffu, v, 4);
        v += __shfl_down_sync(0xffffffffu, v, 2);
        v += __shfl_down_sync(0xffffffffu, v, 1);
        if (lane == 0) atomicAdd(&g_acc, v);
    }
}

__global__ void k_final(float* out) {
    out[0] = (float)(-g_acc / (double)N_);
}

// ---------------------------------------------------------------------------
extern "C" void kernel_launch(void* const* d_in, const int* in_sizes, int n_in,
                              void* d_out, int out_size) {
    const float* y_pred = (const float*)d_in[0];
    const float* y_true = (const float*)d_in[1];

    // 102,400 threads: (plane, h-chunk, w/4)
    k_p12<<<(B_ * D_ * 8 * WG_) / 256, 256>>>(y_true, y_pred);

    // 122,880 threads: (b, d-chunk, h, w/4)
    k_p3<<<(B_ * 8 * H_ * WG_) / 256, 256>>>();

    k_final<<<1, 1>>>((float*)d_out);
}